// round 9
// baseline (speedup 1.0000x reference)
#include <cuda_runtime.h>
#include <cuda_fp16.h>
#include <cstdint>
#include <cstring>

#define N_NODES_MAX 100000
#define EDGE_MAX    1600000
#define DIM 128

// bit-cast helpers (fold to register moves)
__device__ __forceinline__ unsigned h2_to_u32(__half2 h) {
    unsigned u; memcpy(&u, &h, 4); return u;
}
__device__ __forceinline__ __half2 u32_to_h2(unsigned u) {
    __half2 h; memcpy(&h, &u, 4); return h;
}
__device__ __forceinline__ uint32_t smem_u32(const void* p) {
    uint32_t a;
    asm("{ .reg .u64 t; cvta.to.shared.u64 t, %1; cvt.u32.u64 %0, t; }" : "=r"(a) : "l"(p));
    return a;
}

#define LDSM_X4(r0, r1, r2, r3, addr)                                         \
    asm volatile("ldmatrix.sync.aligned.m8n8.x4.shared.b16 {%0,%1,%2,%3}, [%4];" \
                 : "=r"(r0), "=r"(r1), "=r"(r2), "=r"(r3) : "r"(addr))

#define MMA16816(c, a0, a1, a2, a3, b0, b1)                                   \
    asm volatile("mma.sync.aligned.m16n8k16.row.col.f32.f16.f16.f32 "         \
                 "{%0,%1,%2,%3}, {%4,%5,%6,%7}, {%8,%9}, {%0,%1,%2,%3};"      \
                 : "+f"(c[0]), "+f"(c[1]), "+f"(c[2]), "+f"(c[3])             \
                 : "r"(a0), "r"(a1), "r"(a2), "r"(a3), "r"(b0), "r"(b1))

// scratch (allocation-free rule: __device__ globals)
__device__ __half   g_Th[(size_t)N_NODES_MAX * DIM];  // transformed features (fp16)
__device__ __half   g_Wh[DIM * DIM];                  // fp16 copy of W
__device__ unsigned g_cnt[N_NODES_MAX];
__device__ unsigned g_off[N_NODES_MAX];
__device__ unsigned g_cur[N_NODES_MAX];
__device__ unsigned g_bsum[256];
__device__ uint2    g_sorted[EDGE_MAX];               // (src, weight_bits) sorted by dst

// ---------------------------------------------------------------------------
// Kernel 0: one-time W f32 -> fp16 (runs once per launch on side stream)
// ---------------------------------------------------------------------------
__global__ void convert_w_kernel(const float* __restrict__ W)
{
    int i = blockIdx.x * blockDim.x + threadIdx.x;   // 4096 threads, float4 each
    float4 v = *reinterpret_cast<const float4*>(&W[i * 4]);
    uint2 u = make_uint2(h2_to_u32(__floats2half2_rn(v.x, v.y)),
                         h2_to_u32(__floats2half2_rn(v.z, v.w)));
    *reinterpret_cast<uint2*>(&g_Wh[i * 4]) = u;
}

// ---------------------------------------------------------------------------
// Kernel 1: T = node_emb @ W^T via HMMA (fp16 in, f32 acc, fp16 out).
// W comes preconverted from g_Wh (uint4 copy, no cvt, half the traffic).
// ---------------------------------------------------------------------------
#define SMS 136  // smem row stride in halves

__global__ __launch_bounds__(256, 2)
void transform_mma_kernel(const float* __restrict__ E, int n_rows)
{
    extern __shared__ __half sm[];
    __half* As = sm;               // [128][SMS]
    __half* Ws = sm + 128 * SMS;   // [128][SMS]

    const int tid  = threadIdx.x;
    const int row0 = blockIdx.x * 128;

    // E tile: load f32, convert to fp16 (zero-padded past n_rows)
#pragma unroll
    for (int i = 0; i < 16; i++) {
        int idx = tid + i * 256;       // 0..4095
        int r   = idx >> 5;            // 0..127
        int c4  = idx & 31;            // float4 col
        float4 v = make_float4(0.f, 0.f, 0.f, 0.f);
        int er = row0 + r;
        if (er < n_rows) v = *reinterpret_cast<const float4*>(&E[(size_t)er * DIM + c4 * 4]);
        uint2 ue = make_uint2(h2_to_u32(__floats2half2_rn(v.x, v.y)),
                              h2_to_u32(__floats2half2_rn(v.z, v.w)));
        *reinterpret_cast<uint2*>(&As[r * SMS + c4 * 4]) = ue;
    }
    // W tile: straight uint4 copy of fp16 (128 rows x 16 uint4)
#pragma unroll
    for (int i = 0; i < 8; i++) {
        int idx = tid + i * 256;       // 0..2047
        int r   = idx >> 4;            // 0..127
        int c8  = idx & 15;            // uint4 col (8 halves)
        uint4 u = *reinterpret_cast<const uint4*>(&g_Wh[r * DIM + c8 * 8]);
        *reinterpret_cast<uint4*>(&Ws[r * SMS + c8 * 8]) = u;
    }
    __syncthreads();

    const int lane = tid & 31;
    const int warp = tid >> 5;
    const int r0   = warp * 16;

    uint32_t a_base = smem_u32(&As[(r0 + (lane & 15)) * SMS + ((lane >> 4) * 8)]);
    int brow = (lane & 7) + ((lane & 16) ? 8 : 0);
    int bcol = ((lane >> 3) & 1) * 8;
    uint32_t b_base = smem_u32(&Ws[brow * SMS + bcol]);

    float c[16][4];
#pragma unroll
    for (int j = 0; j < 16; j++)
#pragma unroll
        for (int q = 0; q < 4; q++) c[j][q] = 0.f;

#pragma unroll
    for (int k0 = 0; k0 < 128; k0 += 16) {
        uint32_t a0, a1, a2, a3;
        LDSM_X4(a0, a1, a2, a3, a_base + k0 * 2);
#pragma unroll
        for (int np = 0; np < 8; np++) {
            uint32_t b0, b1, b2, b3;
            LDSM_X4(b0, b1, b2, b3, b_base + (np * 16 * SMS + k0) * 2);
            MMA16816(c[2 * np],     a0, a1, a2, a3, b0, b1);
            MMA16816(c[2 * np + 1], a0, a1, a2, a3, b2, b3);
        }
    }

    const int g = lane >> 2, t = lane & 3;
    const int rowA = row0 + r0 + g;
    const int rowB = rowA + 8;
#pragma unroll
    for (int j = 0; j < 16; j++) {
        __half2 h01 = __floats2half2_rn(c[j][0], c[j][1]);
        __half2 h23 = __floats2half2_rn(c[j][2], c[j][3]);
        int col = j * 8 + 2 * t;
        if (rowA < n_rows)
            *reinterpret_cast<__half2*>(&g_Th[(size_t)rowA * DIM + col]) = h01;
        if (rowB < n_rows)
            *reinterpret_cast<__half2*>(&g_Th[(size_t)rowB * DIM + col]) = h23;
    }
}

// ---------------------------------------------------------------------------
// Sort pipeline: histogram -> scan1(shuffle) -> scan3(fused base) -> bucket
// ---------------------------------------------------------------------------
__global__ void hist_kernel(const int* __restrict__ dst, int n_edges)
{
    int i = blockIdx.x * blockDim.x + threadIdx.x;
    int e0 = i * 4;
    if (e0 + 4 <= n_edges) {
        int4 d4 = *reinterpret_cast<const int4*>(dst + e0);
        atomicAdd(&g_cnt[d4.x], 1u);
        atomicAdd(&g_cnt[d4.y], 1u);
        atomicAdd(&g_cnt[d4.z], 1u);
        atomicAdd(&g_cnt[d4.w], 1u);
    } else {
        for (int e = e0; e < n_edges; e++) atomicAdd(&g_cnt[dst[e]], 1u);
    }
}

__global__ __launch_bounds__(1024)
void scan1_kernel(int n)
{
    __shared__ unsigned wsum[32];
    const int t    = threadIdx.x;
    const int lane = t & 31;
    const int warp = t >> 5;
    int i = blockIdx.x * 1024 + t;
    unsigned v = (i < n) ? g_cnt[i] : 0u;

    // warp inclusive scan
    unsigned x = v;
#pragma unroll
    for (int o = 1; o < 32; o <<= 1) {
        unsigned y = __shfl_up_sync(0xffffffffu, x, o);
        if (lane >= o) x += y;
    }
    if (lane == 31) wsum[warp] = x;
    __syncthreads();
    if (warp == 0) {
        unsigned s = wsum[lane];
#pragma unroll
        for (int o = 1; o < 32; o <<= 1) {
            unsigned y = __shfl_up_sync(0xffffffffu, s, o);
            if (lane >= o) s += y;
        }
        wsum[lane] = s;
    }
    __syncthreads();
    unsigned base = (warp > 0) ? wsum[warp - 1] : 0u;
    unsigned incl = x + base;
    if (i < n) g_off[i] = incl - v;
    if (t == 1023) g_bsum[blockIdx.x] = incl;
}

// scan3 with fused chunk-base reduction
__global__ __launch_bounds__(1024)
void scan3_kernel(int n)
{
    __shared__ unsigned sbase;
    int t = threadIdx.x;
    if (t < 32) {
        unsigned s = 0;
        int bid = blockIdx.x;
        for (int b = t; b < bid; b += 32) s += g_bsum[b];
#pragma unroll
        for (int o = 16; o; o >>= 1) s += __shfl_down_sync(0xffffffffu, s, o);
        if (t == 0) sbase = s;
    }
    __syncthreads();
    int i = blockIdx.x * 1024 + t;
    if (i < n) {
        unsigned o = g_off[i] + sbase;
        g_off[i] = o;
        g_cur[i] = o;
    }
}

__global__ void bucket_kernel(const int* __restrict__ src,
                              const int* __restrict__ dst,
                              const float* __restrict__ ew,
                              int n_edges)
{
    int i = blockIdx.x * blockDim.x + threadIdx.x;
    int e0 = i * 4;
    if (e0 + 4 <= n_edges) {
        int4   s4 = *reinterpret_cast<const int4*>(src + e0);
        int4   d4 = *reinterpret_cast<const int4*>(dst + e0);
        float4 w4 = *reinterpret_cast<const float4*>(ew + e0);
        unsigned p0 = atomicAdd(&g_cur[d4.x], 1u);
        unsigned p1 = atomicAdd(&g_cur[d4.y], 1u);
        unsigned p2 = atomicAdd(&g_cur[d4.z], 1u);
        unsigned p3 = atomicAdd(&g_cur[d4.w], 1u);
        g_sorted[p0] = make_uint2((unsigned)s4.x, __float_as_uint(w4.x));
        g_sorted[p1] = make_uint2((unsigned)s4.y, __float_as_uint(w4.y));
        g_sorted[p2] = make_uint2((unsigned)s4.z, __float_as_uint(w4.z));
        g_sorted[p3] = make_uint2((unsigned)s4.w, __float_as_uint(w4.w));
    } else {
        for (int e = e0; e < n_edges; e++) {
            int d = dst[e];
            unsigned pos = atomicAdd(&g_cur[d], 1u);
            g_sorted[pos] = make_uint2((unsigned)src[e], __float_as_uint(ew[e]));
        }
    }
}

// ---------------------------------------------------------------------------
// Aggregation: one warp per dst node; 8 edges in flight (uint4 pair loads),
// fp16 gather, f32 accumulate, STG.128 out.
// ---------------------------------------------------------------------------
__device__ __forceinline__ void agg_one(float4& acc, unsigned srcn, unsigned wbits, int lane)
{
    uint2 h = *reinterpret_cast<const uint2*>(&g_Th[(size_t)srcn * DIM + lane * 4]);
    float w = __uint_as_float(wbits);
    float2 va = __half22float2(u32_to_h2(h.x));
    float2 vb = __half22float2(u32_to_h2(h.y));
    acc.x += va.x * w; acc.y += va.y * w; acc.z += vb.x * w; acc.w += vb.y * w;
}

__global__ __launch_bounds__(256)
void agg_kernel(float* __restrict__ out, int n_nodes, int n_edges)
{
    int node = (int)((blockIdx.x * (unsigned)blockDim.x + threadIdx.x) >> 5);
    int lane = threadIdx.x & 31;
    if (node >= n_nodes) return;

    unsigned start = g_off[node];
    unsigned end   = (node + 1 < n_nodes) ? g_off[node + 1] : (unsigned)n_edges;

    float4 a0 = make_float4(0.f, 0.f, 0.f, 0.f);
    float4 a1 = a0, a2 = a0, a3 = a0;
    float4 a4 = a0, a5 = a0, a6 = a0, a7 = a0;

    unsigned e = start;
    // peel to even e so uint4 loads of g_sorted are 16B-aligned
    if ((e & 1u) && e < end) { agg_one(a0, g_sorted[e].x, g_sorted[e].y, lane); e++; }

    for (; e + 8 <= end; e += 8) {
        uint4 q0 = *reinterpret_cast<const uint4*>(&g_sorted[e + 0]);  // edges e,e+1
        uint4 q1 = *reinterpret_cast<const uint4*>(&g_sorted[e + 2]);
        uint4 q2 = *reinterpret_cast<const uint4*>(&g_sorted[e + 4]);
        uint4 q3 = *reinterpret_cast<const uint4*>(&g_sorted[e + 6]);
        // 8 independent gathers in flight
        uint2 h0 = *reinterpret_cast<const uint2*>(&g_Th[(size_t)q0.x * DIM + lane * 4]);
        uint2 h1 = *reinterpret_cast<const uint2*>(&g_Th[(size_t)q0.z * DIM + lane * 4]);
        uint2 h2 = *reinterpret_cast<const uint2*>(&g_Th[(size_t)q1.x * DIM + lane * 4]);
        uint2 h3 = *reinterpret_cast<const uint2*>(&g_Th[(size_t)q1.z * DIM + lane * 4]);
        uint2 h4 = *reinterpret_cast<const uint2*>(&g_Th[(size_t)q2.x * DIM + lane * 4]);
        uint2 h5 = *reinterpret_cast<const uint2*>(&g_Th[(size_t)q2.z * DIM + lane * 4]);
        uint2 h6 = *reinterpret_cast<const uint2*>(&g_Th[(size_t)q3.x * DIM + lane * 4]);
        uint2 h7 = *reinterpret_cast<const uint2*>(&g_Th[(size_t)q3.z * DIM + lane * 4]);

        float w0 = __uint_as_float(q0.y), w1 = __uint_as_float(q0.w);
        float w2 = __uint_as_float(q1.y), w3 = __uint_as_float(q1.w);
        float w4 = __uint_as_float(q2.y), w5 = __uint_as_float(q2.w);
        float w6 = __uint_as_float(q3.y), w7 = __uint_as_float(q3.w);

        float2 t;
        t = __half22float2(u32_to_h2(h0.x)); a0.x += t.x * w0; a0.y += t.y * w0;
        t = __half22float2(u32_to_h2(h0.y)); a0.z += t.x * w0; a0.w += t.y * w0;
        t = __half22float2(u32_to_h2(h1.x)); a1.x += t.x * w1; a1.y += t.y * w1;
        t = __half22float2(u32_to_h2(h1.y)); a1.z += t.x * w1; a1.w += t.y * w1;
        t = __half22float2(u32_to_h2(h2.x)); a2.x += t.x * w2; a2.y += t.y * w2;
        t = __half22float2(u32_to_h2(h2.y)); a2.z += t.x * w2; a2.w += t.y * w2;
        t = __half22float2(u32_to_h2(h3.x)); a3.x += t.x * w3; a3.y += t.y * w3;
        t = __half22float2(u32_to_h2(h3.y)); a3.z += t.x * w3; a3.w += t.y * w3;
        t = __half22float2(u32_to_h2(h4.x)); a4.x += t.x * w4; a4.y += t.y * w4;
        t = __half22float2(u32_to_h2(h4.y)); a4.z += t.x * w4; a4.w += t.y * w4;
        t = __half22float2(u32_to_h2(h5.x)); a5.x += t.x * w5; a5.y += t.y * w5;
        t = __half22float2(u32_to_h2(h5.y)); a5.z += t.x * w5; a5.w += t.y * w5;
        t = __half22float2(u32_to_h2(h6.x)); a6.x += t.x * w6; a6.y += t.y * w6;
        t = __half22float2(u32_to_h2(h6.y)); a6.z += t.x * w6; a6.w += t.y * w6;
        t = __half22float2(u32_to_h2(h7.x)); a7.x += t.x * w7; a7.y += t.y * w7;
        t = __half22float2(u32_to_h2(h7.y)); a7.z += t.x * w7; a7.w += t.y * w7;
    }
    for (; e < end; e++) agg_one(a0, g_sorted[e].x, g_sorted[e].y, lane);

    float4 r;
    r.x = ((a0.x + a1.x) + (a2.x + a3.x)) + ((a4.x + a5.x) + (a6.x + a7.x));
    r.y = ((a0.y + a1.y) + (a2.y + a3.y)) + ((a4.y + a5.y) + (a6.y + a7.y));
    r.z = ((a0.z + a1.z) + (a2.z + a3.z)) + ((a4.z + a5.z) + (a6.z + a7.z));
    r.w = ((a0.w + a1.w) + (a2.w + a3.w)) + ((a4.w + a5.w) + (a6.w + a7.w));
    *reinterpret_cast<float4*>(&out[(size_t)node * DIM + lane * 4]) = r;
}

// ---------------------------------------------------------------------------
// Launch: W-convert + GEMM on side stream, sort chain on main (fork/join).
// ---------------------------------------------------------------------------
extern "C" void kernel_launch(void* const* d_in, const int* in_sizes, int n_in,
                              void* d_out, int out_size)
{
    const float* node_emb = (const float*)d_in[0];
    const float* ew       = (const float*)d_in[1];
    const int*   src      = (const int*)d_in[2];
    const int*   dst      = (const int*)d_in[3];
    const float* W        = (const float*)d_in[4];
    float*       out      = (float*)d_out;

    const int n_nodes = in_sizes[0] / DIM;
    const int n_edges = in_sizes[1];

    void* cnt_ptr = nullptr;
    cudaGetSymbolAddress(&cnt_ptr, g_cnt);

    cudaStream_t s;
    cudaStreamCreateWithFlags(&s, cudaStreamNonBlocking);
    cudaEvent_t evFork, evJoin;
    cudaEventCreateWithFlags(&evFork, cudaEventDisableTiming);
    cudaEventCreateWithFlags(&evJoin, cudaEventDisableTiming);

    cudaEventRecord(evFork, 0);
    cudaStreamWaitEvent(s, evFork, 0);

    // --- side stream: W convert + tensor-core transform ---
    convert_w_kernel<<<16, 256, 0, s>>>(W);  // 4096 threads x float4 = 16384 elems
    const int smem_bytes = 2 * 128 * SMS * (int)sizeof(__half);  // 69632
    cudaFuncSetAttribute(transform_mma_kernel,
                         cudaFuncAttributeMaxDynamicSharedMemorySize, smem_bytes);
    int gemm_blocks = (n_nodes + 127) / 128;
    transform_mma_kernel<<<gemm_blocks, 256, smem_bytes, s>>>(node_emb, n_nodes);
    cudaEventRecord(evJoin, s);

    // --- main stream: sort pipeline ---
    cudaMemsetAsync(cnt_ptr, 0, (size_t)n_nodes * sizeof(unsigned));
    int eb4 = (n_edges / 4 + 255) / 256 + 1;
    hist_kernel<<<eb4, 256>>>(dst, n_edges);
    int nchunks = (n_nodes + 1023) / 1024;
    scan1_kernel<<<nchunks, 1024>>>(n_nodes);
    scan3_kernel<<<nchunks, 1024>>>(n_nodes);
    bucket_kernel<<<eb4, 256>>>(src, dst, ew, n_edges);

    cudaStreamWaitEvent(0, evJoin, 0);
    int ab = (n_nodes * 32 + 255) / 256;
    agg_kernel<<<ab, 256>>>(out, n_nodes, n_edges);

    cudaStreamCaptureStatus cap = cudaStreamCaptureStatusNone;
    cudaStreamIsCapturing(s, &cap);
    if (cap == cudaStreamCaptureStatusNone) {
        cudaEventDestroy(evFork);
        cudaEventDestroy(evJoin);
        cudaStreamDestroy(s);
    }
}

// round 10
// speedup vs baseline: 1.1237x; 1.1237x over previous
#include <cuda_runtime.h>
#include <cuda_fp16.h>
#include <cstdint>
#include <cstring>

#define N_NODES_MAX 100000
#define EDGE_MAX    1600000
#define DIM 128

// bit-cast helpers (fold to register moves)
__device__ __forceinline__ unsigned h2_to_u32(__half2 h) {
    unsigned u; memcpy(&u, &h, 4); return u;
}
__device__ __forceinline__ __half2 u32_to_h2(unsigned u) {
    __half2 h; memcpy(&h, &u, 4); return h;
}
__device__ __forceinline__ uint32_t smem_u32(const void* p) {
    uint32_t a;
    asm("{ .reg .u64 t; cvta.to.shared.u64 t, %1; cvt.u32.u64 %0, t; }" : "=r"(a) : "l"(p));
    return a;
}

#define LDSM_X4(r0, r1, r2, r3, addr)                                         \
    asm volatile("ldmatrix.sync.aligned.m8n8.x4.shared.b16 {%0,%1,%2,%3}, [%4];" \
                 : "=r"(r0), "=r"(r1), "=r"(r2), "=r"(r3) : "r"(addr))

#define MMA16816(c, a0, a1, a2, a3, b0, b1)                                   \
    asm volatile("mma.sync.aligned.m16n8k16.row.col.f32.f16.f16.f32 "         \
                 "{%0,%1,%2,%3}, {%4,%5,%6,%7}, {%8,%9}, {%0,%1,%2,%3};"      \
                 : "+f"(c[0]), "+f"(c[1]), "+f"(c[2]), "+f"(c[3])             \
                 : "r"(a0), "r"(a1), "r"(a2), "r"(a3), "r"(b0), "r"(b1))

// scratch (allocation-free rule: __device__ globals)
__device__ __half   g_Th[(size_t)N_NODES_MAX * DIM];  // transformed features (fp16)
__device__ unsigned g_cnt[N_NODES_MAX];
__device__ unsigned g_off[N_NODES_MAX];
__device__ unsigned g_cur[N_NODES_MAX];
__device__ unsigned g_bsum[256];
__device__ uint2    g_sorted[EDGE_MAX];               // (src, weight_bits) sorted by dst

// ---------------------------------------------------------------------------
// Kernel 1: T = node_emb @ W^T via HMMA (fp16 in, f32 acc, fp16 out).
// (R8 version: inline W load+convert — GEMM is off the critical path.)
// ---------------------------------------------------------------------------
#define SMS 136  // smem row stride in halves

__global__ __launch_bounds__(256, 2)
void transform_mma_kernel(const float* __restrict__ E, const float* __restrict__ W, int n_rows)
{
    extern __shared__ __half sm[];
    __half* As = sm;               // [128][SMS]
    __half* Ws = sm + 128 * SMS;   // [128][SMS]

    const int tid  = threadIdx.x;
    const int row0 = blockIdx.x * 128;

#pragma unroll
    for (int i = 0; i < 16; i++) {
        int idx = tid + i * 256;
        int r   = idx >> 5;
        int c4  = idx & 31;
        float4 v = make_float4(0.f, 0.f, 0.f, 0.f);
        int er = row0 + r;
        if (er < n_rows) v = *reinterpret_cast<const float4*>(&E[(size_t)er * DIM + c4 * 4]);
        uint2 ue = make_uint2(h2_to_u32(__floats2half2_rn(v.x, v.y)),
                              h2_to_u32(__floats2half2_rn(v.z, v.w)));
        *reinterpret_cast<uint2*>(&As[r * SMS + c4 * 4]) = ue;

        float4 wv = *reinterpret_cast<const float4*>(&W[(size_t)r * DIM + c4 * 4]);
        uint2 uw = make_uint2(h2_to_u32(__floats2half2_rn(wv.x, wv.y)),
                              h2_to_u32(__floats2half2_rn(wv.z, wv.w)));
        *reinterpret_cast<uint2*>(&Ws[r * SMS + c4 * 4]) = uw;
    }
    __syncthreads();

    const int lane = tid & 31;
    const int warp = tid >> 5;
    const int r0   = warp * 16;

    uint32_t a_base = smem_u32(&As[(r0 + (lane & 15)) * SMS + ((lane >> 4) * 8)]);
    int brow = (lane & 7) + ((lane & 16) ? 8 : 0);
    int bcol = ((lane >> 3) & 1) * 8;
    uint32_t b_base = smem_u32(&Ws[brow * SMS + bcol]);

    float c[16][4];
#pragma unroll
    for (int j = 0; j < 16; j++)
#pragma unroll
        for (int q = 0; q < 4; q++) c[j][q] = 0.f;

#pragma unroll
    for (int k0 = 0; k0 < 128; k0 += 16) {
        uint32_t a0, a1, a2, a3;
        LDSM_X4(a0, a1, a2, a3, a_base + k0 * 2);
#pragma unroll
        for (int np = 0; np < 8; np++) {
            uint32_t b0, b1, b2, b3;
            LDSM_X4(b0, b1, b2, b3, b_base + (np * 16 * SMS + k0) * 2);
            MMA16816(c[2 * np],     a0, a1, a2, a3, b0, b1);
            MMA16816(c[2 * np + 1], a0, a1, a2, a3, b2, b3);
        }
    }

    const int g = lane >> 2, t = lane & 3;
    const int rowA = row0 + r0 + g;
    const int rowB = rowA + 8;
#pragma unroll
    for (int j = 0; j < 16; j++) {
        __half2 h01 = __floats2half2_rn(c[j][0], c[j][1]);
        __half2 h23 = __floats2half2_rn(c[j][2], c[j][3]);
        int col = j * 8 + 2 * t;
        if (rowA < n_rows)
            *reinterpret_cast<__half2*>(&g_Th[(size_t)rowA * DIM + col]) = h01;
        if (rowB < n_rows)
            *reinterpret_cast<__half2*>(&g_Th[(size_t)rowB * DIM + col]) = h23;
    }
}

// ---------------------------------------------------------------------------
// Sort pipeline: histogram -> scan1(shuffle) -> scan3(fused base) -> bucket
// ---------------------------------------------------------------------------
__global__ void hist_kernel(const int* __restrict__ dst, int n_edges)
{
    int i = blockIdx.x * blockDim.x + threadIdx.x;
    int e0 = i * 4;
    if (e0 + 4 <= n_edges) {
        int4 d4 = *reinterpret_cast<const int4*>(dst + e0);
        atomicAdd(&g_cnt[d4.x], 1u);
        atomicAdd(&g_cnt[d4.y], 1u);
        atomicAdd(&g_cnt[d4.z], 1u);
        atomicAdd(&g_cnt[d4.w], 1u);
    } else {
        for (int e = e0; e < n_edges; e++) atomicAdd(&g_cnt[dst[e]], 1u);
    }
}

__global__ __launch_bounds__(1024)
void scan1_kernel(int n)
{
    __shared__ unsigned wsum[32];
    const int t    = threadIdx.x;
    const int lane = t & 31;
    const int warp = t >> 5;
    int i = blockIdx.x * 1024 + t;
    unsigned v = (i < n) ? g_cnt[i] : 0u;

    unsigned x = v;
#pragma unroll
    for (int o = 1; o < 32; o <<= 1) {
        unsigned y = __shfl_up_sync(0xffffffffu, x, o);
        if (lane >= o) x += y;
    }
    if (lane == 31) wsum[warp] = x;
    __syncthreads();
    if (warp == 0) {
        unsigned s = wsum[lane];
#pragma unroll
        for (int o = 1; o < 32; o <<= 1) {
            unsigned y = __shfl_up_sync(0xffffffffu, s, o);
            if (lane >= o) s += y;
        }
        wsum[lane] = s;
    }
    __syncthreads();
    unsigned base = (warp > 0) ? wsum[warp - 1] : 0u;
    unsigned incl = x + base;
    if (i < n) g_off[i] = incl - v;
    if (t == 1023) g_bsum[blockIdx.x] = incl;
}

__global__ __launch_bounds__(1024)
void scan3_kernel(int n)
{
    __shared__ unsigned sbase;
    int t = threadIdx.x;
    if (t < 32) {
        unsigned s = 0;
        int bid = blockIdx.x;
        for (int b = t; b < bid; b += 32) s += g_bsum[b];
#pragma unroll
        for (int o = 16; o; o >>= 1) s += __shfl_down_sync(0xffffffffu, s, o);
        if (t == 0) sbase = s;
    }
    __syncthreads();
    int i = blockIdx.x * 1024 + t;
    if (i < n) {
        unsigned o = g_off[i] + sbase;
        g_off[i] = o;
        g_cur[i] = o;
    }
}

__global__ void bucket_kernel(const int* __restrict__ src,
                              const int* __restrict__ dst,
                              const float* __restrict__ ew,
                              int n_edges)
{
    int i = blockIdx.x * blockDim.x + threadIdx.x;
    int e0 = i * 4;
    if (e0 + 4 <= n_edges) {
        int4   s4 = *reinterpret_cast<const int4*>(src + e0);
        int4   d4 = *reinterpret_cast<const int4*>(dst + e0);
        float4 w4 = *reinterpret_cast<const float4*>(ew + e0);
        unsigned p0 = atomicAdd(&g_cur[d4.x], 1u);
        unsigned p1 = atomicAdd(&g_cur[d4.y], 1u);
        unsigned p2 = atomicAdd(&g_cur[d4.z], 1u);
        unsigned p3 = atomicAdd(&g_cur[d4.w], 1u);
        g_sorted[p0] = make_uint2((unsigned)s4.x, __float_as_uint(w4.x));
        g_sorted[p1] = make_uint2((unsigned)s4.y, __float_as_uint(w4.y));
        g_sorted[p2] = make_uint2((unsigned)s4.z, __float_as_uint(w4.z));
        g_sorted[p3] = make_uint2((unsigned)s4.w, __float_as_uint(w4.w));
    } else {
        for (int e = e0; e < n_edges; e++) {
            int d = dst[e];
            unsigned pos = atomicAdd(&g_cur[d], 1u);
            g_sorted[pos] = make_uint2((unsigned)src[e], __float_as_uint(ew[e]));
        }
    }
}

// ---------------------------------------------------------------------------
// Aggregation: one warp per dst node; 4 edges per iter (2x uint4 metadata
// loads), fp16 gather, f32 accumulate, STG.128 out. (R8 register footprint.)
// ---------------------------------------------------------------------------
__device__ __forceinline__ void agg_one(float4& acc, unsigned srcn, unsigned wbits, int lane)
{
    uint2 h = *reinterpret_cast<const uint2*>(&g_Th[(size_t)srcn * DIM + lane * 4]);
    float w = __uint_as_float(wbits);
    float2 va = __half22float2(u32_to_h2(h.x));
    float2 vb = __half22float2(u32_to_h2(h.y));
    acc.x += va.x * w; acc.y += va.y * w; acc.z += vb.x * w; acc.w += vb.y * w;
}

__global__ __launch_bounds__(256)
void agg_kernel(float* __restrict__ out, int n_nodes, int n_edges)
{
    int node = (int)((blockIdx.x * (unsigned)blockDim.x + threadIdx.x) >> 5);
    int lane = threadIdx.x & 31;
    if (node >= n_nodes) return;

    unsigned start = g_off[node];
    unsigned end   = (node + 1 < n_nodes) ? g_off[node + 1] : (unsigned)n_edges;

    float4 a0 = make_float4(0.f, 0.f, 0.f, 0.f);
    float4 a1 = a0, a2 = a0, a3 = a0;

    unsigned e = start;
    // peel to even e so uint4 loads of g_sorted are 16B-aligned
    if ((e & 1u) && e < end) { agg_one(a0, g_sorted[e].x, g_sorted[e].y, lane); e++; }

    for (; e + 4 <= end; e += 4) {
        uint4 q0 = *reinterpret_cast<const uint4*>(&g_sorted[e + 0]);  // edges e, e+1
        uint4 q1 = *reinterpret_cast<const uint4*>(&g_sorted[e + 2]);  // edges e+2, e+3
        uint2 h0 = *reinterpret_cast<const uint2*>(&g_Th[(size_t)q0.x * DIM + lane * 4]);
        uint2 h1 = *reinterpret_cast<const uint2*>(&g_Th[(size_t)q0.z * DIM + lane * 4]);
        uint2 h2 = *reinterpret_cast<const uint2*>(&g_Th[(size_t)q1.x * DIM + lane * 4]);
        uint2 h3 = *reinterpret_cast<const uint2*>(&g_Th[(size_t)q1.z * DIM + lane * 4]);
        float w0 = __uint_as_float(q0.y), w1 = __uint_as_float(q0.w);
        float w2 = __uint_as_float(q1.y), w3 = __uint_as_float(q1.w);
        float2 t;
        t = __half22float2(u32_to_h2(h0.x)); a0.x += t.x * w0; a0.y += t.y * w0;
        t = __half22float2(u32_to_h2(h0.y)); a0.z += t.x * w0; a0.w += t.y * w0;
        t = __half22float2(u32_to_h2(h1.x)); a1.x += t.x * w1; a1.y += t.y * w1;
        t = __half22float2(u32_to_h2(h1.y)); a1.z += t.x * w1; a1.w += t.y * w1;
        t = __half22float2(u32_to_h2(h2.x)); a2.x += t.x * w2; a2.y += t.y * w2;
        t = __half22float2(u32_to_h2(h2.y)); a2.z += t.x * w2; a2.w += t.y * w2;
        t = __half22float2(u32_to_h2(h3.x)); a3.x += t.x * w3; a3.y += t.y * w3;
        t = __half22float2(u32_to_h2(h3.y)); a3.z += t.x * w3; a3.w += t.y * w3;
    }
    for (; e < end; e++) agg_one(a0, g_sorted[e].x, g_sorted[e].y, lane);

    float4 r;
    r.x = (a0.x + a1.x) + (a2.x + a3.x);
    r.y = (a0.y + a1.y) + (a2.y + a3.y);
    r.z = (a0.z + a1.z) + (a2.z + a3.z);
    r.w = (a0.w + a1.w) + (a2.w + a3.w);
    *reinterpret_cast<float4*>(&out[(size_t)node * DIM + lane * 4]) = r;
}

// ---------------------------------------------------------------------------
// Launch: GEMM on side stream overlapped with sort chain (fork/join).
// ---------------------------------------------------------------------------
extern "C" void kernel_launch(void* const* d_in, const int* in_sizes, int n_in,
                              void* d_out, int out_size)
{
    const float* node_emb = (const float*)d_in[0];
    const float* ew       = (const float*)d_in[1];
    const int*   src      = (const int*)d_in[2];
    const int*   dst      = (const int*)d_in[3];
    const float* W        = (const float*)d_in[4];
    float*       out      = (float*)d_out;

    const int n_nodes = in_sizes[0] / DIM;
    const int n_edges = in_sizes[1];

    void* cnt_ptr = nullptr;
    cudaGetSymbolAddress(&cnt_ptr, g_cnt);

    cudaStream_t s;
    cudaStreamCreateWithFlags(&s, cudaStreamNonBlocking);
    cudaEvent_t evFork, evJoin;
    cudaEventCreateWithFlags(&evFork, cudaEventDisableTiming);
    cudaEventCreateWithFlags(&evJoin, cudaEventDisableTiming);

    cudaEventRecord(evFork, 0);
    cudaStreamWaitEvent(s, evFork, 0);

    // --- side stream: tensor-core transform ---
    const int smem_bytes = 2 * 128 * SMS * (int)sizeof(__half);  // 69632
    cudaFuncSetAttribute(transform_mma_kernel,
                         cudaFuncAttributeMaxDynamicSharedMemorySize, smem_bytes);
    int gemm_blocks = (n_nodes + 127) / 128;
    transform_mma_kernel<<<gemm_blocks, 256, smem_bytes, s>>>(node_emb, W, n_nodes);
    cudaEventRecord(evJoin, s);

    // --- main stream: sort pipeline ---
    cudaMemsetAsync(cnt_ptr, 0, (size_t)n_nodes * sizeof(unsigned));
    int eb4 = (n_edges / 4 + 255) / 256 + 1;
    hist_kernel<<<eb4, 256>>>(dst, n_edges);
    int nchunks = (n_nodes + 1023) / 1024;
    scan1_kernel<<<nchunks, 1024>>>(n_nodes);
    scan3_kernel<<<nchunks, 1024>>>(n_nodes);
    bucket_kernel<<<eb4, 256>>>(src, dst, ew, n_edges);

    cudaStreamWaitEvent(0, evJoin, 0);
    int ab = (n_nodes * 32 + 255) / 256;
    agg_kernel<<<ab, 256>>>(out, n_nodes, n_edges);

    cudaStreamCaptureStatus cap = cudaStreamCaptureStatusNone;
    cudaStreamIsCapturing(s, &cap);
    if (cap == cudaStreamCaptureStatusNone) {
        cudaEventDestroy(evFork);
        cudaEventDestroy(evJoin);
        cudaStreamDestroy(s);
    }
}

// round 11
// speedup vs baseline: 1.1862x; 1.0556x over previous
#include <cuda_runtime.h>
#include <cuda_fp16.h>
#include <cstdint>
#include <cstring>

#define N_NODES_MAX 100000
#define EDGE_MAX    1600000
#define DIM 128

// bit-cast helpers (fold to register moves)
__device__ __forceinline__ unsigned h2_to_u32(__half2 h) {
    unsigned u; memcpy(&u, &h, 4); return u;
}
__device__ __forceinline__ __half2 u32_to_h2(unsigned u) {
    __half2 h; memcpy(&h, &u, 4); return h;
}
__device__ __forceinline__ uint32_t smem_u32(const void* p) {
    uint32_t a;
    asm("{ .reg .u64 t; cvta.to.shared.u64 t, %1; cvt.u32.u64 %0, t; }" : "=r"(a) : "l"(p));
    return a;
}

#define LDSM_X4(r0, r1, r2, r3, addr)                                         \
    asm volatile("ldmatrix.sync.aligned.m8n8.x4.shared.b16 {%0,%1,%2,%3}, [%4];" \
                 : "=r"(r0), "=r"(r1), "=r"(r2), "=r"(r3) : "r"(addr))

#define MMA16816(c, a0, a1, a2, a3, b0, b1)                                   \
    asm volatile("mma.sync.aligned.m16n8k16.row.col.f32.f16.f16.f32 "         \
                 "{%0,%1,%2,%3}, {%4,%5,%6,%7}, {%8,%9}, {%0,%1,%2,%3};"      \
                 : "+f"(c[0]), "+f"(c[1]), "+f"(c[2]), "+f"(c[3])             \
                 : "r"(a0), "r"(a1), "r"(a2), "r"(a3), "r"(b0), "r"(b1))

// scratch (allocation-free rule: __device__ globals)
__device__ __half   g_Th[(size_t)N_NODES_MAX * DIM];  // transformed features (fp16)
__device__ unsigned g_cnt[N_NODES_MAX];
__device__ unsigned g_off[N_NODES_MAX];
__device__ unsigned g_cur[N_NODES_MAX];
__device__ unsigned g_bsum[256];
__device__ uint2    g_sorted[EDGE_MAX];               // (src, weight_bits) sorted by dst

// ---------------------------------------------------------------------------
// Kernel 1: T = node_emb @ W^T via HMMA (fp16 in, f32 acc, fp16 out). (R8)
// ---------------------------------------------------------------------------
#define SMS 136  // smem row stride in halves

__global__ __launch_bounds__(256, 2)
void transform_mma_kernel(const float* __restrict__ E, const float* __restrict__ W, int n_rows)
{
    extern __shared__ __half sm[];
    __half* As = sm;               // [128][SMS]
    __half* Ws = sm + 128 * SMS;   // [128][SMS]

    const int tid  = threadIdx.x;
    const int row0 = blockIdx.x * 128;

#pragma unroll
    for (int i = 0; i < 16; i++) {
        int idx = tid + i * 256;
        int r   = idx >> 5;
        int c4  = idx & 31;
        float4 v = make_float4(0.f, 0.f, 0.f, 0.f);
        int er = row0 + r;
        if (er < n_rows) v = *reinterpret_cast<const float4*>(&E[(size_t)er * DIM + c4 * 4]);
        uint2 ue = make_uint2(h2_to_u32(__floats2half2_rn(v.x, v.y)),
                              h2_to_u32(__floats2half2_rn(v.z, v.w)));
        *reinterpret_cast<uint2*>(&As[r * SMS + c4 * 4]) = ue;

        float4 wv = *reinterpret_cast<const float4*>(&W[(size_t)r * DIM + c4 * 4]);
        uint2 uw = make_uint2(h2_to_u32(__floats2half2_rn(wv.x, wv.y)),
                              h2_to_u32(__floats2half2_rn(wv.z, wv.w)));
        *reinterpret_cast<uint2*>(&Ws[r * SMS + c4 * 4]) = uw;
    }
    __syncthreads();

    const int lane = tid & 31;
    const int warp = tid >> 5;
    const int r0   = warp * 16;

    uint32_t a_base = smem_u32(&As[(r0 + (lane & 15)) * SMS + ((lane >> 4) * 8)]);
    int brow = (lane & 7) + ((lane & 16) ? 8 : 0);
    int bcol = ((lane >> 3) & 1) * 8;
    uint32_t b_base = smem_u32(&Ws[brow * SMS + bcol]);

    float c[16][4];
#pragma unroll
    for (int j = 0; j < 16; j++)
#pragma unroll
        for (int q = 0; q < 4; q++) c[j][q] = 0.f;

#pragma unroll
    for (int k0 = 0; k0 < 128; k0 += 16) {
        uint32_t a0, a1, a2, a3;
        LDSM_X4(a0, a1, a2, a3, a_base + k0 * 2);
#pragma unroll
        for (int np = 0; np < 8; np++) {
            uint32_t b0, b1, b2, b3;
            LDSM_X4(b0, b1, b2, b3, b_base + (np * 16 * SMS + k0) * 2);
            MMA16816(c[2 * np],     a0, a1, a2, a3, b0, b1);
            MMA16816(c[2 * np + 1], a0, a1, a2, a3, b2, b3);
        }
    }

    const int g = lane >> 2, t = lane & 3;
    const int rowA = row0 + r0 + g;
    const int rowB = rowA + 8;
#pragma unroll
    for (int j = 0; j < 16; j++) {
        __half2 h01 = __floats2half2_rn(c[j][0], c[j][1]);
        __half2 h23 = __floats2half2_rn(c[j][2], c[j][3]);
        int col = j * 8 + 2 * t;
        if (rowA < n_rows)
            *reinterpret_cast<__half2*>(&g_Th[(size_t)rowA * DIM + col]) = h01;
        if (rowB < n_rows)
            *reinterpret_cast<__half2*>(&g_Th[(size_t)rowB * DIM + col]) = h23;
    }
}

// ---------------------------------------------------------------------------
// Sort pipeline: histogram -> scan1(shuffle) -> scan3(fused base) -> bucket
// ---------------------------------------------------------------------------
__global__ void hist_kernel(const int* __restrict__ dst, int n_edges)
{
    int i = blockIdx.x * blockDim.x + threadIdx.x;
    int e0 = i * 4;
    if (e0 + 4 <= n_edges) {
        int4 d4 = *reinterpret_cast<const int4*>(dst + e0);
        atomicAdd(&g_cnt[d4.x], 1u);
        atomicAdd(&g_cnt[d4.y], 1u);
        atomicAdd(&g_cnt[d4.z], 1u);
        atomicAdd(&g_cnt[d4.w], 1u);
    } else {
        for (int e = e0; e < n_edges; e++) atomicAdd(&g_cnt[dst[e]], 1u);
    }
}

__global__ __launch_bounds__(1024)
void scan1_kernel(int n)
{
    __shared__ unsigned wsum[32];
    const int t    = threadIdx.x;
    const int lane = t & 31;
    const int warp = t >> 5;
    int i = blockIdx.x * 1024 + t;
    unsigned v = (i < n) ? g_cnt[i] : 0u;

    unsigned x = v;
#pragma unroll
    for (int o = 1; o < 32; o <<= 1) {
        unsigned y = __shfl_up_sync(0xffffffffu, x, o);
        if (lane >= o) x += y;
    }
    if (lane == 31) wsum[warp] = x;
    __syncthreads();
    if (warp == 0) {
        unsigned s = wsum[lane];
#pragma unroll
        for (int o = 1; o < 32; o <<= 1) {
            unsigned y = __shfl_up_sync(0xffffffffu, s, o);
            if (lane >= o) s += y;
        }
        wsum[lane] = s;
    }
    __syncthreads();
    unsigned base = (warp > 0) ? wsum[warp - 1] : 0u;
    unsigned incl = x + base;
    if (i < n) g_off[i] = incl - v;
    if (t == 1023) g_bsum[blockIdx.x] = incl;
}

__global__ __launch_bounds__(1024)
void scan3_kernel(int n)
{
    __shared__ unsigned sbase;
    int t = threadIdx.x;
    if (t < 32) {
        unsigned s = 0;
        int bid = blockIdx.x;
        for (int b = t; b < bid; b += 32) s += g_bsum[b];
#pragma unroll
        for (int o = 16; o; o >>= 1) s += __shfl_down_sync(0xffffffffu, s, o);
        if (t == 0) sbase = s;
    }
    __syncthreads();
    int i = blockIdx.x * 1024 + t;
    if (i < n) {
        unsigned o = g_off[i] + sbase;
        g_off[i] = o;
        g_cur[i] = o;
    }
}

__global__ void bucket_kernel(const int* __restrict__ src,
                              const int* __restrict__ dst,
                              const float* __restrict__ ew,
                              int n_edges)
{
    int i = blockIdx.x * blockDim.x + threadIdx.x;
    int e0 = i * 4;
    if (e0 + 4 <= n_edges) {
        int4   s4 = *reinterpret_cast<const int4*>(src + e0);
        int4   d4 = *reinterpret_cast<const int4*>(dst + e0);
        float4 w4 = *reinterpret_cast<const float4*>(ew + e0);
        unsigned p0 = atomicAdd(&g_cur[d4.x], 1u);
        unsigned p1 = atomicAdd(&g_cur[d4.y], 1u);
        unsigned p2 = atomicAdd(&g_cur[d4.z], 1u);
        unsigned p3 = atomicAdd(&g_cur[d4.w], 1u);
        g_sorted[p0] = make_uint2((unsigned)s4.x, __float_as_uint(w4.x));
        g_sorted[p1] = make_uint2((unsigned)s4.y, __float_as_uint(w4.y));
        g_sorted[p2] = make_uint2((unsigned)s4.z, __float_as_uint(w4.z));
        g_sorted[p3] = make_uint2((unsigned)s4.w, __float_as_uint(w4.w));
    } else {
        for (int e = e0; e < n_edges; e++) {
            int d = dst[e];
            unsigned pos = atomicAdd(&g_cur[d], 1u);
            g_sorted[pos] = make_uint2((unsigned)src[e], __float_as_uint(ew[e]));
        }
    }
}

// ---------------------------------------------------------------------------
// Aggregation: one warp per dst node; R8 loop shape (4x uint2 metadata, 4
// independent gathers, 4 accumulators) + metadata prefetch pipeline.
// ---------------------------------------------------------------------------
__device__ __forceinline__ void agg_one(float4& acc, unsigned srcn, unsigned wbits, int lane)
{
    uint2 h = *reinterpret_cast<const uint2*>(&g_Th[(size_t)srcn * DIM + lane * 4]);
    float w = __uint_as_float(wbits);
    float2 va = __half22float2(u32_to_h2(h.x));
    float2 vb = __half22float2(u32_to_h2(h.y));
    acc.x += va.x * w; acc.y += va.y * w; acc.z += vb.x * w; acc.w += vb.y * w;
}

__global__ __launch_bounds__(256)
void agg_kernel(float* __restrict__ out, int n_nodes, int n_edges)
{
    int node = (int)((blockIdx.x * (unsigned)blockDim.x + threadIdx.x) >> 5);
    int lane = threadIdx.x & 31;
    if (node >= n_nodes) return;

    unsigned start = g_off[node];
    unsigned end   = (node + 1 < n_nodes) ? g_off[node + 1] : (unsigned)n_edges;

    float4 a0 = make_float4(0.f, 0.f, 0.f, 0.f);
    float4 a1 = a0, a2 = a0, a3 = a0;

    unsigned e = start;
    if (e + 4 <= end) {
        // prologue: first group's metadata
        uint2 m0 = g_sorted[e + 0];
        uint2 m1 = g_sorted[e + 1];
        uint2 m2 = g_sorted[e + 2];
        uint2 m3 = g_sorted[e + 3];

        for (; e + 8 <= end; e += 4) {
            // prefetch next group's metadata (independent of current gathers)
            uint2 n0 = g_sorted[e + 4];
            uint2 n1 = g_sorted[e + 5];
            uint2 n2 = g_sorted[e + 6];
            uint2 n3 = g_sorted[e + 7];

            uint2 h0 = *reinterpret_cast<const uint2*>(&g_Th[(size_t)m0.x * DIM + lane * 4]);
            uint2 h1 = *reinterpret_cast<const uint2*>(&g_Th[(size_t)m1.x * DIM + lane * 4]);
            uint2 h2 = *reinterpret_cast<const uint2*>(&g_Th[(size_t)m2.x * DIM + lane * 4]);
            uint2 h3 = *reinterpret_cast<const uint2*>(&g_Th[(size_t)m3.x * DIM + lane * 4]);
            float w0 = __uint_as_float(m0.y), w1 = __uint_as_float(m1.y);
            float w2 = __uint_as_float(m2.y), w3 = __uint_as_float(m3.y);
            float2 t;
            t = __half22float2(u32_to_h2(h0.x)); a0.x += t.x * w0; a0.y += t.y * w0;
            t = __half22float2(u32_to_h2(h0.y)); a0.z += t.x * w0; a0.w += t.y * w0;
            t = __half22float2(u32_to_h2(h1.x)); a1.x += t.x * w1; a1.y += t.y * w1;
            t = __half22float2(u32_to_h2(h1.y)); a1.z += t.x * w1; a1.w += t.y * w1;
            t = __half22float2(u32_to_h2(h2.x)); a2.x += t.x * w2; a2.y += t.y * w2;
            t = __half22float2(u32_to_h2(h2.y)); a2.z += t.x * w2; a2.w += t.y * w2;
            t = __half22float2(u32_to_h2(h3.x)); a3.x += t.x * w3; a3.y += t.y * w3;
            t = __half22float2(u32_to_h2(h3.y)); a3.z += t.x * w3; a3.w += t.y * w3;

            m0 = n0; m1 = n1; m2 = n2; m3 = n3;
        }

        // epilogue: process final prefetched group
        {
            uint2 h0 = *reinterpret_cast<const uint2*>(&g_Th[(size_t)m0.x * DIM + lane * 4]);
            uint2 h1 = *reinterpret_cast<const uint2*>(&g_Th[(size_t)m1.x * DIM + lane * 4]);
            uint2 h2 = *reinterpret_cast<const uint2*>(&g_Th[(size_t)m2.x * DIM + lane * 4]);
            uint2 h3 = *reinterpret_cast<const uint2*>(&g_Th[(size_t)m3.x * DIM + lane * 4]);
            float w0 = __uint_as_float(m0.y), w1 = __uint_as_float(m1.y);
            float w2 = __uint_as_float(m2.y), w3 = __uint_as_float(m3.y);
            float2 t;
            t = __half22float2(u32_to_h2(h0.x)); a0.x += t.x * w0; a0.y += t.y * w0;
            t = __half22float2(u32_to_h2(h0.y)); a0.z += t.x * w0; a0.w += t.y * w0;
            t = __half22float2(u32_to_h2(h1.x)); a1.x += t.x * w1; a1.y += t.y * w1;
            t = __half22float2(u32_to_h2(h1.y)); a1.z += t.x * w1; a1.w += t.y * w1;
            t = __half22float2(u32_to_h2(h2.x)); a2.x += t.x * w2; a2.y += t.y * w2;
            t = __half22float2(u32_to_h2(h2.y)); a2.z += t.x * w2; a2.w += t.y * w2;
            t = __half22float2(u32_to_h2(h3.x)); a3.x += t.x * w3; a3.y += t.y * w3;
            t = __half22float2(u32_to_h2(h3.y)); a3.z += t.x * w3; a3.w += t.y * w3;
            e += 4;
        }
    }
    for (; e < end; e++) agg_one(a0, g_sorted[e].x, g_sorted[e].y, lane);

    float4 r;
    r.x = (a0.x + a1.x) + (a2.x + a3.x);
    r.y = (a0.y + a1.y) + (a2.y + a3.y);
    r.z = (a0.z + a1.z) + (a2.z + a3.z);
    r.w = (a0.w + a1.w) + (a2.w + a3.w);
    *reinterpret_cast<float4*>(&out[(size_t)node * DIM + lane * 4]) = r;
}

// ---------------------------------------------------------------------------
// Launch: GEMM on side stream overlapped with sort chain (fork/join).
// ---------------------------------------------------------------------------
extern "C" void kernel_launch(void* const* d_in, const int* in_sizes, int n_in,
                              void* d_out, int out_size)
{
    const float* node_emb = (const float*)d_in[0];
    const float* ew       = (const float*)d_in[1];
    const int*   src      = (const int*)d_in[2];
    const int*   dst      = (const int*)d_in[3];
    const float* W        = (const float*)d_in[4];
    float*       out      = (float*)d_out;

    const int n_nodes = in_sizes[0] / DIM;
    const int n_edges = in_sizes[1];

    void* cnt_ptr = nullptr;
    cudaGetSymbolAddress(&cnt_ptr, g_cnt);

    cudaStream_t s;
    cudaStreamCreateWithFlags(&s, cudaStreamNonBlocking);
    cudaEvent_t evFork, evJoin;
    cudaEventCreateWithFlags(&evFork, cudaEventDisableTiming);
    cudaEventCreateWithFlags(&evJoin, cudaEventDisableTiming);

    cudaEventRecord(evFork, 0);
    cudaStreamWaitEvent(s, evFork, 0);

    // --- side stream: tensor-core transform ---
    const int smem_bytes = 2 * 128 * SMS * (int)sizeof(__half);  // 69632
    cudaFuncSetAttribute(transform_mma_kernel,
                         cudaFuncAttributeMaxDynamicSharedMemorySize, smem_bytes);
    int gemm_blocks = (n_nodes + 127) / 128;
    transform_mma_kernel<<<gemm_blocks, 256, smem_bytes, s>>>(node_emb, W, n_nodes);
    cudaEventRecord(evJoin, s);

    // --- main stream: sort pipeline ---
    cudaMemsetAsync(cnt_ptr, 0, (size_t)n_nodes * sizeof(unsigned));
    int eb4 = (n_edges / 4 + 255) / 256 + 1;
    hist_kernel<<<eb4, 256>>>(dst, n_edges);
    int nchunks = (n_nodes + 1023) / 1024;
    scan1_kernel<<<nchunks, 1024>>>(n_nodes);
    scan3_kernel<<<nchunks, 1024>>>(n_nodes);
    bucket_kernel<<<eb4, 256>>>(src, dst, ew, n_edges);

    cudaStreamWaitEvent(0, evJoin, 0);
    int ab = (n_nodes * 32 + 255) / 256;
    agg_kernel<<<ab, 256>>>(out, n_nodes, n_edges);

    cudaStreamCaptureStatus cap = cudaStreamCaptureStatusNone;
    cudaStreamIsCapturing(s, &cap);
    if (cap == cudaStreamCaptureStatusNone) {
        cudaEventDestroy(evFork);
        cudaEventDestroy(evJoin);
        cudaStreamDestroy(s);
    }
}